// round 15
// baseline (speedup 1.0000x reference)
#include <cuda_runtime.h>
#include <cuda_fp16.h>
#include <math.h>
#include <stdint.h>

#define TSEQ 4096
#define CDIM 1024
#define HDIM 64
#define NB   4

__device__ __half g_q[NB * TSEQ * HDIM];
__device__ __half g_k[NB * TSEQ * HDIM];
__device__ __half g_v[NB * TSEQ * HDIM];
__device__ __half g_wh[CDIM * 192];          // fused fp16 W: [k][mat*64+n]
__device__ float  g_osum[NB * TSEQ * HDIM];
__device__ float  g_lsum[NB * TSEQ];
__device__ unsigned g_cnt[NB * 64];          // per-(b,m) completion counters

// packh2(lo, hi): lo -> low 16 bits, hi -> high 16 bits (RNE)
__device__ __forceinline__ unsigned packh2(float lo, float hi) {
    unsigned d;
    asm("cvt.rn.f16x2.f32 %0, %1, %2;" : "=r"(d) : "f"(hi), "f"(lo));
    return d;
}

__device__ __forceinline__ void mma16(float* d, const unsigned* a, unsigned b0, unsigned b1) {
    asm volatile(
        "mma.sync.aligned.m16n8k16.row.col.f32.f16.f16.f32 "
        "{%0,%1,%2,%3}, {%4,%5,%6,%7}, {%8,%9}, {%0,%1,%2,%3};"
        : "+f"(d[0]), "+f"(d[1]), "+f"(d[2]), "+f"(d[3])
        : "r"(a[0]), "r"(a[1]), "r"(a[2]), "r"(a[3]), "r"(b0), "r"(b1));
}

#define LDSM_X4(r0, r1, r2, r3, addr) \
    asm volatile("ldmatrix.sync.aligned.m8n8.x4.shared.b16 {%0,%1,%2,%3}, [%4];" \
                 : "=r"(r0), "=r"(r1), "=r"(r2), "=r"(r3) : "r"(addr))
#define LDSM_X4_T(r0, r1, r2, r3, addr) \
    asm volatile("ldmatrix.sync.aligned.m8n8.x4.trans.shared.b16 {%0,%1,%2,%3}, [%4];" \
                 : "=r"(r0), "=r"(r1), "=r"(r2), "=r"(r3) : "r"(addr))

__device__ __forceinline__ uint32_t smem_u32(const void* p) {
    uint32_t a;
    asm("{ .reg .u64 t; cvta.to.shared.u64 t, %1; cvt.u32.u64 %0, t; }"
        : "=r"(a) : "l"(p));
    return a;
}
__device__ __forceinline__ void cpa16(uint32_t dst, const void* src) {
    asm volatile("cp.async.ca.shared.global [%0], [%1], 16;" :: "r"(dst), "l"(src) : "memory");
}

// ---------------------------------------------------------------------------
// W fp32 -> fp16 (RNE) once + zero accumulators & counters. grid 256 x 256.
// ---------------------------------------------------------------------------
__global__ void wcvt_kernel(const float* __restrict__ W0,
                            const float* __restrict__ W1,
                            const float* __restrict__ W2)
{
    int t = blockIdx.x * 256 + threadIdx.x;      // 0..65535
    int k = t >> 6, n = t & 63;
    g_wh[k * 192 +       n] = __float2half_rn(W0[t]);
    g_wh[k * 192 +  64 + n] = __float2half_rn(W1[t]);
    g_wh[k * 192 + 128 + n] = __float2half_rn(W2[t]);

    float4 z = make_float4(0.f, 0.f, 0.f, 0.f);
#pragma unroll
    for (int i = 0; i < 4; i++)                   // 4*65536 = 262144 float4
        ((float4*)g_osum)[t + i * 65536] = z;
    if (t < NB * TSEQ / 4) ((float4*)g_lsum)[t] = z;
    if (t < NB * 64) g_cnt[t] = 0u;
}

// ---------------------------------------------------------------------------
// Fused QKV projection (round-14 version, unchanged).
// ---------------------------------------------------------------------------
#define XSH 72     // halves per x row (144 B, odd multiple of 16B)
#define WSH 200    // halves per W row (400 B, odd multiple of 16B)

__global__ __launch_bounds__(256, 2) void proj_kernel(const float* __restrict__ x)
{
    extern __shared__ __half smp[];
    const uint32_t xb = smem_u32(smp);              // x: 2 x [64*XSH]
    const uint32_t XBYTES = 64 * XSH * 2;           // 9216
    const uint32_t wb = xb + 2 * XBYTES;            // W: 2 x [64*WSH]
    const uint32_t WBYTES = 64 * WSH * 2;           // 25600

    const int tid = threadIdx.x;
    const int lane = tid & 31, w = tid >> 5;
    const int mw = w & 1, nw = w >> 1;
    const int l4 = lane >> 2, lm = lane & 3;
    const int j8 = lane >> 3, r8 = lane & 7;
    const int r0 = blockIdx.x * 64;

    const int xrow = tid >> 2;            // 64 rows, 4 threads/row
    const int xk0 = (tid & 3) * 16;       // 16 k-cols per thread

    float acc[2][6][4];
#pragma unroll
    for (int a = 0; a < 2; a++)
#pragma unroll
        for (int b = 0; b < 6; b++)
#pragma unroll
            for (int c = 0; c < 4; c++) acc[a][b][c] = 0.f;

    // ---- prologue: chunk 0 -> buffers 0 ----
    {
        const float* xs = &x[(size_t)(r0 + xrow) * CDIM + xk0];
        float4 v0 = ((const float4*)xs)[0], v1 = ((const float4*)xs)[1];
        float4 v2 = ((const float4*)xs)[2], v3 = ((const float4*)xs)[3];
        uint32_t a = xb + (uint32_t)(xrow * XSH + xk0) * 2;
        asm volatile("st.shared.v4.b32 [%0], {%1,%2,%3,%4};" :: "r"(a),
            "r"(packh2(v0.x, v0.y)), "r"(packh2(v0.z, v0.w)),
            "r"(packh2(v1.x, v1.y)), "r"(packh2(v1.z, v1.w)) : "memory");
        asm volatile("st.shared.v4.b32 [%0], {%1,%2,%3,%4};" :: "r"(a + 16),
            "r"(packh2(v2.x, v2.y)), "r"(packh2(v2.z, v2.w)),
            "r"(packh2(v3.x, v3.y)), "r"(packh2(v3.z, v3.w)) : "memory");
#pragma unroll
        for (int i = 0; i < 6; i++) {
            int c = tid + i * 256;                // 0..1535
            int kr = c / 24, col8 = (c % 24) * 8;
            cpa16(wb + (uint32_t)(kr * WSH + col8) * 2, &g_wh[(size_t)kr * 192 + col8]);
        }
        asm volatile("cp.async.commit_group;" ::: "memory");
    }

#pragma unroll 1
    for (int c = 0; c < 16; c++) {
        const int buf = c & 1;
        const bool pre = (c + 1 < 16);

        float4 xr0, xr1, xr2, xr3;
        if (pre) {
            const float* xs = &x[(size_t)(r0 + xrow) * CDIM + (c + 1) * 64 + xk0];
            xr0 = ((const float4*)xs)[0]; xr1 = ((const float4*)xs)[1];
            xr2 = ((const float4*)xs)[2]; xr3 = ((const float4*)xs)[3];
        }

        asm volatile("cp.async.wait_group 0;" ::: "memory");
        __syncthreads();

        if (pre) {
            const int nb = buf ^ 1;
#pragma unroll
            for (int i = 0; i < 6; i++) {
                int cc = tid + i * 256;
                int kr = cc / 24, col8 = (cc % 24) * 8;
                cpa16(wb + nb * WBYTES + (uint32_t)(kr * WSH + col8) * 2,
                      &g_wh[(size_t)((c + 1) * 64 + kr) * 192 + col8]);
            }
            asm volatile("cp.async.commit_group;" ::: "memory");
            uint32_t a = xb + nb * XBYTES + (uint32_t)(xrow * XSH + xk0) * 2;
            asm volatile("st.shared.v4.b32 [%0], {%1,%2,%3,%4};" :: "r"(a),
                "r"(packh2(xr0.x, xr0.y)), "r"(packh2(xr0.z, xr0.w)),
                "r"(packh2(xr1.x, xr1.y)), "r"(packh2(xr1.z, xr1.w)) : "memory");
            asm volatile("st.shared.v4.b32 [%0], {%1,%2,%3,%4};" :: "r"(a + 16),
                "r"(packh2(xr2.x, xr2.y)), "r"(packh2(xr2.z, xr2.w)),
                "r"(packh2(xr3.x, xr3.y)), "r"(packh2(xr3.z, xr3.w)) : "memory");
        }

        const uint32_t xbuf = xb + buf * XBYTES;
        const uint32_t wbuf = wb + buf * WBYTES;
#pragma unroll
        for (int ks = 0; ks < 4; ks++) {
            const int k0 = 16 * ks;
            unsigned af[2][4];
#pragma unroll
            for (int mf = 0; mf < 2; mf++) {
                uint32_t a = xbuf + (uint32_t)((32 * mw + 16 * mf + ((j8 >> 1) << 3) + r8) * XSH
                                                + k0 + ((j8 & 1) << 3)) * 2;
                unsigned t0, t1, t2, t3;
                LDSM_X4(t0, t1, t2, t3, a);
                af[mf][0] = t0; af[mf][1] = t2; af[mf][2] = t1; af[mf][3] = t3;
            }
#pragma unroll
            for (int nb2 = 0; nb2 < 3; nb2++) {
                const int n0 = 48 * nw + 16 * nb2;
                uint32_t a = wbuf + (uint32_t)((k0 + ((j8 & 1) << 3) + r8) * WSH
                                                + n0 + ((j8 >> 1) << 3)) * 2;
                unsigned b0, b1, b2, b3;
                LDSM_X4_T(b0, b1, b2, b3, a);
#pragma unroll
                for (int mf = 0; mf < 2; mf++) {
                    mma16(acc[mf][2 * nb2],     af[mf], b0, b1);
                    mma16(acc[mf][2 * nb2 + 1], af[mf], b2, b3);
                }
            }
        }
    }

#pragma unroll
    for (int mf = 0; mf < 2; mf++)
#pragma unroll
        for (int nf = 0; nf < 6; nf++) {
            int colg = 48 * nw + 8 * nf;
            __half* dst = (colg >= 128) ? g_v : (colg >= 64 ? g_k : g_q);
            int col = (colg & 63) + 2 * lm;
            int rg = r0 + 32 * mw + 16 * mf + l4;
            *(unsigned*)&dst[(size_t)rg * HDIM + col] = packh2(acc[mf][nf][0], acc[mf][nf][1]);
            *(unsigned*)&dst[(size_t)(rg + 8) * HDIM + col] = packh2(acc[mf][nf][2], acc[mf][nf][3]);
        }
}

// ---------------------------------------------------------------------------
// Split-K fp16 flash attention + fused last-unit normalization.
// Tiles m<32: 1 unit; m>=32: 2 units. Counter decides who normalizes.
// ---------------------------------------------------------------------------
#define KP 72
#define CFAC 0.18033688011112042f   // 0.125 * log2(e)

__global__ __launch_bounds__(256, 2) void attn_kernel(float* __restrict__ out)
{
    extern __shared__ __half smh[];
    __shared__ int s_done;
    const uint32_t sb = smem_u32(smh);
    const uint32_t KBYTES = 64 * KP * 2;

    const int bid = blockIdx.x;
    int b, m, c0, c1;
    if (bid < 128) {
        b = bid & 3; m = 32 + (bid >> 2); c0 = 0; c1 = 32;
    } else {
        int i = bid - 128, j = i >> 3, r = i & 7;
        b = r & 3;
        if ((r & 4) == 0) { m = 31 - j; c0 = 0; }
        else              { m = 63 - j; c0 = 32; }
        c1 = m + 1;
    }
    const int q0 = m * 64;

    const int tid = threadIdx.x;
    const int lane = tid & 31, w = tid >> 5;
    const int mw = w & 3, nw = w >> 2;
    const int l4 = lane >> 2, lm = lane & 3;
    const int rb = 16 * mw;
    const int j8 = lane >> 3, r8 = lane & 7;

    const __half* Q = g_q + (size_t)b * TSEQ * HDIM;
    const __half* K = g_k + (size_t)b * TSEQ * HDIM;
    const __half* V = g_v + (size_t)b * TSEQ * HDIM;

    unsigned qf[4][4];
#pragma unroll
    for (int ks = 0; ks < 4; ks++) {
        const __half* q1 = &Q[(size_t)(q0 + rb + l4) * HDIM + 16 * ks + 2 * lm];
        const __half* q2 = &Q[(size_t)(q0 + rb + 8 + l4) * HDIM + 16 * ks + 2 * lm];
        qf[ks][0] = *(const unsigned*)q1;
        qf[ks][1] = *(const unsigned*)q2;
        qf[ks][2] = *(const unsigned*)(q1 + 8);
        qf[ks][3] = *(const unsigned*)(q2 + 8);
    }

    float oacc[8][4];
#pragma unroll
    for (int i = 0; i < 8; i++)
#pragma unroll
        for (int j = 0; j < 4; j++) oacc[i][j] = 0.f;
    float lsum1 = 0.f, lsum2 = 0.f;

    const int srow0 = tid >> 3, srow1 = (tid + 256) >> 3;
    const int sch = (tid & 7) * 8;

    {
        const __half* Kg = &K[(size_t)c0 * 64 * HDIM];
        const __half* Vg = &V[(size_t)c0 * 64 * HDIM];
        cpa16(sb + (uint32_t)(srow0 * KP + sch) * 2, &Kg[srow0 * HDIM + sch]);
        cpa16(sb + (uint32_t)(srow1 * KP + sch) * 2, &Kg[srow1 * HDIM + sch]);
        cpa16(sb + 2 * KBYTES + (uint32_t)(srow0 * KP + sch) * 2, &Vg[srow0 * HDIM + sch]);
        cpa16(sb + 2 * KBYTES + (uint32_t)(srow1 * KP + sch) * 2, &Vg[srow1 * HDIM + sch]);
        asm volatile("cp.async.commit_group;" ::: "memory");
    }

#pragma unroll 1
    for (int n = c0; n < c1; n++) {
        const int buf = (n - c0) & 1;
        const uint32_t kb_s = sb + buf * KBYTES;
        const uint32_t vb_s = sb + (2 + buf) * KBYTES;

        asm volatile("cp.async.wait_group 0;" ::: "memory");
        __syncthreads();

        if (n + 1 < c1) {
            const int nbuf = 1 - buf;
            const __half* Kg = &K[(size_t)(n + 1) * 64 * HDIM];
            const __half* Vg = &V[(size_t)(n + 1) * 64 * HDIM];
            const uint32_t kd = sb + nbuf * KBYTES;
            const uint32_t vd = sb + (2 + nbuf) * KBYTES;
            cpa16(kd + (uint32_t)(srow0 * KP + sch) * 2, &Kg[srow0 * HDIM + sch]);
            cpa16(kd + (uint32_t)(srow1 * KP + sch) * 2, &Kg[srow1 * HDIM + sch]);
            cpa16(vd + (uint32_t)(srow0 * KP + sch) * 2, &Vg[srow0 * HDIM + sch]);
            cpa16(vd + (uint32_t)(srow1 * KP + sch) * 2, &Vg[srow1 * HDIM + sch]);
            asm volatile("cp.async.commit_group;" ::: "memory");
        }

        float s[4][4];
#pragma unroll
        for (int i = 0; i < 4; i++)
#pragma unroll
            for (int j = 0; j < 4; j++) s[i][j] = 0.f;
#pragma unroll
        for (int np = 0; np < 2; np++) {
            const int n0 = 32 * nw + 16 * np;
#pragma unroll
            for (int ks = 0; ks < 4; ks++) {
                const int h0 = 16 * ks;
                uint32_t ka = kb_s + (uint32_t)((n0 + ((j8 >> 1) << 3) + r8) * KP
                                                + h0 + ((j8 & 1) << 3)) * 2;
                unsigned k0r, k1r, k2r, k3r;
                LDSM_X4(k0r, k1r, k2r, k3r, ka);
                mma16(s[2 * np],     qf[ks], k0r, k1r);
                mma16(s[2 * np + 1], qf[ks], k2r, k3r);
            }
        }

        if (n == m) {
#pragma unroll
            for (int nf = 0; nf < 4; nf++) {
                int lc = 32 * nw + 8 * nf + 2 * lm;
                int lr1 = rb + l4, lr2 = lr1 + 8;
                s[nf][0] = (lc     <= lr1) ? exp2f(s[nf][0] * CFAC) : 0.f;
                s[nf][1] = (lc + 1 <= lr1) ? exp2f(s[nf][1] * CFAC) : 0.f;
                s[nf][2] = (lc     <= lr2) ? exp2f(s[nf][2] * CFAC) : 0.f;
                s[nf][3] = (lc + 1 <= lr2) ? exp2f(s[nf][3] * CFAC) : 0.f;
            }
        } else {
#pragma unroll
            for (int nf = 0; nf < 4; nf++) {
                s[nf][0] = exp2f(s[nf][0] * CFAC);
                s[nf][1] = exp2f(s[nf][1] * CFAC);
                s[nf][2] = exp2f(s[nf][2] * CFAC);
                s[nf][3] = exp2f(s[nf][3] * CFAC);
            }
        }
#pragma unroll
        for (int nf = 0; nf < 4; nf++) {
            lsum1 += s[nf][0] + s[nf][1];
            lsum2 += s[nf][2] + s[nf][3];
        }

        unsigned ap[2][4];
#pragma unroll
        for (int kb = 0; kb < 2; kb++) {
            ap[kb][0] = packh2(s[2 * kb][0],     s[2 * kb][1]);
            ap[kb][1] = packh2(s[2 * kb][2],     s[2 * kb][3]);
            ap[kb][2] = packh2(s[2 * kb + 1][0], s[2 * kb + 1][1]);
            ap[kb][3] = packh2(s[2 * kb + 1][2], s[2 * kb + 1][3]);
        }

#pragma unroll
        for (int kb = 0; kb < 2; kb++) {
            const int k0 = 32 * nw + 16 * kb;
#pragma unroll
            for (int hp = 0; hp < 4; hp++) {
                const int h0 = 16 * hp;
                uint32_t va = vb_s + (uint32_t)((k0 + ((j8 & 1) << 3) + r8) * KP
                                                + h0 + ((j8 >> 1) << 3)) * 2;
                unsigned v0r, v1r, v2r, v3r;
                LDSM_X4_T(v0r, v1r, v2r, v3r, va);
                mma16(oacc[2 * hp],     ap[kb], v0r, v1r);
                mma16(oacc[2 * hp + 1], ap[kb], v2r, v3r);
            }
        }
    }

    // ---- epilogue: atomic-accumulate partials ----
    lsum1 += __shfl_xor_sync(0xffffffffu, lsum1, 1);
    lsum1 += __shfl_xor_sync(0xffffffffu, lsum1, 2);
    lsum2 += __shfl_xor_sync(0xffffffffu, lsum2, 1);
    lsum2 += __shfl_xor_sync(0xffffffffu, lsum2, 2);
    if (lm == 0) {
        atomicAdd(&g_lsum[(size_t)b * TSEQ + q0 + rb + l4], lsum1);
        atomicAdd(&g_lsum[(size_t)b * TSEQ + q0 + rb + 8 + l4], lsum2);
    }
    float* Ob = g_osum + (size_t)b * TSEQ * HDIM;
    const size_t r1 = (size_t)(q0 + rb + l4) * HDIM;
    const size_t r2 = (size_t)(q0 + rb + 8 + l4) * HDIM;
#pragma unroll
    for (int hb = 0; hb < 8; hb++) {
        int col = 8 * hb + 2 * lm;
        atomicAdd(&Ob[r1 + col],     oacc[hb][0]);
        atomicAdd(&Ob[r1 + col + 1], oacc[hb][1]);
        atomicAdd(&Ob[r2 + col],     oacc[hb][2]);
        atomicAdd(&Ob[r2 + col + 1], oacc[hb][3]);
    }

    // ---- fused normalization: last unit for this tile divides + stores ----
    __threadfence();
    __syncthreads();
    if (tid == 0) s_done = (int)atomicAdd(&g_cnt[b * 64 + m], 1u) + 1;
    __syncthreads();
    const int need = (m >= 32) ? 2 : 1;
    if (s_done == need) {
        __threadfence();   // acquire: other unit's fenced writes are visible
        const float4* Os = (const float4*)(g_osum + ((size_t)b * TSEQ + q0) * HDIM);
        const float*  Ls = g_lsum + (size_t)b * TSEQ + q0;
        float4* Og = (float4*)(out + ((size_t)b * TSEQ + q0) * HDIM);
#pragma unroll
        for (int i = 0; i < 4; i++) {
            int idx = tid * 4 + i;               // 0..1023 float4 (64 rows x 16)
            int row = idx >> 4;
            float inv = 1.0f / __ldcg(&Ls[row]);
            float4 o = __ldcg(&Os[idx]);
            Og[idx] = make_float4(o.x * inv, o.y * inv, o.z * inv, o.w * inv);
        }
    }
}

// ---------------------------------------------------------------------------
extern "C" void kernel_launch(void* const* d_in, const int* in_sizes, int n_in,
                              void* d_out, int out_size)
{
    const float* x  = (const float*)d_in[0];
    const float* Wq = (const float*)d_in[1];
    const float* Wk = (const float*)d_in[2];
    const float* Wv = (const float*)d_in[3];
    float* out = (float*)d_out;

    const int proj_smem = 2 * (64 * XSH + 64 * WSH) * 2;   // 69632 B
    const int attn_smem = 4 * 64 * KP * 2;                 // 36864 B
    cudaFuncSetAttribute(proj_kernel, cudaFuncAttributeMaxDynamicSharedMemorySize, proj_smem);
    cudaFuncSetAttribute(attn_kernel, cudaFuncAttributeMaxDynamicSharedMemorySize, attn_smem);

    wcvt_kernel<<<256, 256>>>(Wq, Wk, Wv);
    proj_kernel<<<NB * TSEQ / 64, 256, proj_smem>>>(x);
    attn_kernel<<<384, 256, attn_smem>>>(out);
}

// round 16
// speedup vs baseline: 1.0633x; 1.0633x over previous
#include <cuda_runtime.h>
#include <cuda_fp16.h>
#include <math.h>
#include <stdint.h>

#define TSEQ 4096
#define CDIM 1024
#define HDIM 64
#define NB   4

__device__ __half g_q[NB * TSEQ * HDIM];
__device__ __half g_k[NB * TSEQ * HDIM];
__device__ __half g_v[NB * TSEQ * HDIM];
__device__ __half g_wh[CDIM * 192];          // fused fp16 W: [k][mat*64+n]
__device__ float  g_osum[NB * TSEQ * HDIM];
__device__ float  g_lsum[NB * TSEQ];

// packh2(lo, hi): lo -> low 16 bits, hi -> high 16 bits (RNE)
__device__ __forceinline__ unsigned packh2(float lo, float hi) {
    unsigned d;
    asm("cvt.rn.f16x2.f32 %0, %1, %2;" : "=r"(d) : "f"(hi), "f"(lo));
    return d;
}

__device__ __forceinline__ void mma16(float* d, const unsigned* a, unsigned b0, unsigned b1) {
    asm volatile(
        "mma.sync.aligned.m16n8k16.row.col.f32.f16.f16.f32 "
        "{%0,%1,%2,%3}, {%4,%5,%6,%7}, {%8,%9}, {%0,%1,%2,%3};"
        : "+f"(d[0]), "+f"(d[1]), "+f"(d[2]), "+f"(d[3])
        : "r"(a[0]), "r"(a[1]), "r"(a[2]), "r"(a[3]), "r"(b0), "r"(b1));
}

#define LDSM_X4(r0, r1, r2, r3, addr) \
    asm volatile("ldmatrix.sync.aligned.m8n8.x4.shared.b16 {%0,%1,%2,%3}, [%4];" \
                 : "=r"(r0), "=r"(r1), "=r"(r2), "=r"(r3) : "r"(addr))
#define LDSM_X4_T(r0, r1, r2, r3, addr) \
    asm volatile("ldmatrix.sync.aligned.m8n8.x4.trans.shared.b16 {%0,%1,%2,%3}, [%4];" \
                 : "=r"(r0), "=r"(r1), "=r"(r2), "=r"(r3) : "r"(addr))

__device__ __forceinline__ uint32_t smem_u32(const void* p) {
    uint32_t a;
    asm("{ .reg .u64 t; cvta.to.shared.u64 t, %1; cvt.u32.u64 %0, t; }"
        : "=r"(a) : "l"(p));
    return a;
}
__device__ __forceinline__ void cpa16(uint32_t dst, const void* src) {
    asm volatile("cp.async.ca.shared.global [%0], [%1], 16;" :: "r"(dst), "l"(src) : "memory");
}

// ---------------------------------------------------------------------------
// W fp32 -> fp16 (RNE) once + zero UPPER-HALF accumulators (only m>=32 tiles
// use the atomic path). grid 256 x 256.
// ---------------------------------------------------------------------------
__global__ void wcvt_kernel(const float* __restrict__ W0,
                            const float* __restrict__ W1,
                            const float* __restrict__ W2)
{
    int t = blockIdx.x * 256 + threadIdx.x;      // 0..65535
    int k = t >> 6, n = t & 63;
    g_wh[k * 192 +       n] = __float2half_rn(W0[t]);
    g_wh[k * 192 +  64 + n] = __float2half_rn(W1[t]);
    g_wh[k * 192 + 128 + n] = __float2half_rn(W2[t]);

    float4 z = make_float4(0.f, 0.f, 0.f, 0.f);
#pragma unroll
    for (int i = 0; i < 2; i++) {                 // 131072 float4 = upper half
        int idx = t + i * 65536;
        int b = idx >> 15, rem = idx & 32767;     // 32768 float4 per batch
        int row = 2048 + (rem >> 4);
        ((float4*)g_osum)[(((size_t)b * TSEQ + row) * HDIM >> 2) + (rem & 15)] = z;
    }
    if (t < 2048) {                               // upper-half lsum: 512 f4/batch
        int b = t >> 9, i = t & 511;
        ((float4*)g_lsum)[b * 1024 + 512 + i] = z;
    }
}

// ---------------------------------------------------------------------------
// Fused QKV projection (round-14 version, unchanged).
// ---------------------------------------------------------------------------
#define XSH 72     // halves per x row (144 B, odd multiple of 16B)
#define WSH 200    // halves per W row (400 B, odd multiple of 16B)

__global__ __launch_bounds__(256, 2) void proj_kernel(const float* __restrict__ x)
{
    extern __shared__ __half smp[];
    const uint32_t xb = smem_u32(smp);              // x: 2 x [64*XSH]
    const uint32_t XBYTES = 64 * XSH * 2;           // 9216
    const uint32_t wb = xb + 2 * XBYTES;            // W: 2 x [64*WSH]
    const uint32_t WBYTES = 64 * WSH * 2;           // 25600

    const int tid = threadIdx.x;
    const int lane = tid & 31, w = tid >> 5;
    const int mw = w & 1, nw = w >> 1;
    const int l4 = lane >> 2, lm = lane & 3;
    const int j8 = lane >> 3, r8 = lane & 7;
    const int r0 = blockIdx.x * 64;

    const int xrow = tid >> 2;
    const int xk0 = (tid & 3) * 16;

    float acc[2][6][4];
#pragma unroll
    for (int a = 0; a < 2; a++)
#pragma unroll
        for (int b = 0; b < 6; b++)
#pragma unroll
            for (int c = 0; c < 4; c++) acc[a][b][c] = 0.f;

    // ---- prologue: chunk 0 -> buffers 0 ----
    {
        const float* xs = &x[(size_t)(r0 + xrow) * CDIM + xk0];
        float4 v0 = ((const float4*)xs)[0], v1 = ((const float4*)xs)[1];
        float4 v2 = ((const float4*)xs)[2], v3 = ((const float4*)xs)[3];
        uint32_t a = xb + (uint32_t)(xrow * XSH + xk0) * 2;
        asm volatile("st.shared.v4.b32 [%0], {%1,%2,%3,%4};" :: "r"(a),
            "r"(packh2(v0.x, v0.y)), "r"(packh2(v0.z, v0.w)),
            "r"(packh2(v1.x, v1.y)), "r"(packh2(v1.z, v1.w)) : "memory");
        asm volatile("st.shared.v4.b32 [%0], {%1,%2,%3,%4};" :: "r"(a + 16),
            "r"(packh2(v2.x, v2.y)), "r"(packh2(v2.z, v2.w)),
            "r"(packh2(v3.x, v3.y)), "r"(packh2(v3.z, v3.w)) : "memory");
#pragma unroll
        for (int i = 0; i < 6; i++) {
            int c = tid + i * 256;
            int kr = c / 24, col8 = (c % 24) * 8;
            cpa16(wb + (uint32_t)(kr * WSH + col8) * 2, &g_wh[(size_t)kr * 192 + col8]);
        }
        asm volatile("cp.async.commit_group;" ::: "memory");
    }

#pragma unroll 1
    for (int c = 0; c < 16; c++) {
        const int buf = c & 1;
        const bool pre = (c + 1 < 16);

        float4 xr0, xr1, xr2, xr3;
        if (pre) {
            const float* xs = &x[(size_t)(r0 + xrow) * CDIM + (c + 1) * 64 + xk0];
            xr0 = ((const float4*)xs)[0]; xr1 = ((const float4*)xs)[1];
            xr2 = ((const float4*)xs)[2]; xr3 = ((const float4*)xs)[3];
        }

        asm volatile("cp.async.wait_group 0;" ::: "memory");
        __syncthreads();

        if (pre) {
            const int nb = buf ^ 1;
#pragma unroll
            for (int i = 0; i < 6; i++) {
                int cc = tid + i * 256;
                int kr = cc / 24, col8 = (cc % 24) * 8;
                cpa16(wb + nb * WBYTES + (uint32_t)(kr * WSH + col8) * 2,
                      &g_wh[(size_t)((c + 1) * 64 + kr) * 192 + col8]);
            }
            asm volatile("cp.async.commit_group;" ::: "memory");
            uint32_t a = xb + nb * XBYTES + (uint32_t)(xrow * XSH + xk0) * 2;
            asm volatile("st.shared.v4.b32 [%0], {%1,%2,%3,%4};" :: "r"(a),
                "r"(packh2(xr0.x, xr0.y)), "r"(packh2(xr0.z, xr0.w)),
                "r"(packh2(xr1.x, xr1.y)), "r"(packh2(xr1.z, xr1.w)) : "memory");
            asm volatile("st.shared.v4.b32 [%0], {%1,%2,%3,%4};" :: "r"(a + 16),
                "r"(packh2(xr2.x, xr2.y)), "r"(packh2(xr2.z, xr2.w)),
                "r"(packh2(xr3.x, xr3.y)), "r"(packh2(xr3.z, xr3.w)) : "memory");
        }

        const uint32_t xbuf = xb + buf * XBYTES;
        const uint32_t wbuf = wb + buf * WBYTES;
#pragma unroll
        for (int ks = 0; ks < 4; ks++) {
            const int k0 = 16 * ks;
            unsigned af[2][4];
#pragma unroll
            for (int mf = 0; mf < 2; mf++) {
                uint32_t a = xbuf + (uint32_t)((32 * mw + 16 * mf + ((j8 >> 1) << 3) + r8) * XSH
                                                + k0 + ((j8 & 1) << 3)) * 2;
                unsigned t0, t1, t2, t3;
                LDSM_X4(t0, t1, t2, t3, a);
                af[mf][0] = t0; af[mf][1] = t2; af[mf][2] = t1; af[mf][3] = t3;
            }
#pragma unroll
            for (int nb2 = 0; nb2 < 3; nb2++) {
                const int n0 = 48 * nw + 16 * nb2;
                uint32_t a = wbuf + (uint32_t)((k0 + ((j8 & 1) << 3) + r8) * WSH
                                                + n0 + ((j8 >> 1) << 3)) * 2;
                unsigned b0, b1, b2, b3;
                LDSM_X4_T(b0, b1, b2, b3, a);
#pragma unroll
                for (int mf = 0; mf < 2; mf++) {
                    mma16(acc[mf][2 * nb2],     af[mf], b0, b1);
                    mma16(acc[mf][2 * nb2 + 1], af[mf], b2, b3);
                }
            }
        }
    }

#pragma unroll
    for (int mf = 0; mf < 2; mf++)
#pragma unroll
        for (int nf = 0; nf < 6; nf++) {
            int colg = 48 * nw + 8 * nf;
            __half* dst = (colg >= 128) ? g_v : (colg >= 64 ? g_k : g_q);
            int col = (colg & 63) + 2 * lm;
            int rg = r0 + 32 * mw + 16 * mf + l4;
            *(unsigned*)&dst[(size_t)rg * HDIM + col] = packh2(acc[mf][nf][0], acc[mf][nf][1]);
            *(unsigned*)&dst[(size_t)(rg + 8) * HDIM + col] = packh2(acc[mf][nf][2], acc[mf][nf][3]);
        }
}

// ---------------------------------------------------------------------------
// Split-K fp16 flash attention. m<32 units (complete tiles) pair-reduce via
// smem and write normalized output DIRECTLY (no atomics, no norm pass).
// m>=32 tiles keep the atomic + norm path.
// ---------------------------------------------------------------------------
#define KP 72
#define EXP 66     // exchange pad (floats per row) — odd/2 banks, conflict-free
#define CFAC 0.18033688011112042f   // 0.125 * log2(e)

__global__ __launch_bounds__(256, 2) void attn_kernel(float* __restrict__ out)
{
    extern __shared__ __half smh[];
    const uint32_t sb = smem_u32(smh);
    const uint32_t KBYTES = 64 * KP * 2;

    const int bid = blockIdx.x;
    int b, m, c0, c1;
    if (bid < 128) {
        b = bid & 3; m = 32 + (bid >> 2); c0 = 0; c1 = 32;
    } else {
        int i = bid - 128, j = i >> 3, r = i & 7;
        b = r & 3;
        if ((r & 4) == 0) { m = 31 - j; c0 = 0; }
        else              { m = 63 - j; c0 = 32; }
        c1 = m + 1;
    }
    const int q0 = m * 64;

    const int tid = threadIdx.x;
    const int lane = tid & 31, w = tid >> 5;
    const int mw = w & 3, nw = w >> 2;
    const int l4 = lane >> 2, lm = lane & 3;
    const int rb = 16 * mw;
    const int j8 = lane >> 3, r8 = lane & 7;

    const __half* Q = g_q + (size_t)b * TSEQ * HDIM;
    const __half* K = g_k + (size_t)b * TSEQ * HDIM;
    const __half* V = g_v + (size_t)b * TSEQ * HDIM;

    unsigned qf[4][4];
#pragma unroll
    for (int ks = 0; ks < 4; ks++) {
        const __half* q1 = &Q[(size_t)(q0 + rb + l4) * HDIM + 16 * ks + 2 * lm];
        const __half* q2 = &Q[(size_t)(q0 + rb + 8 + l4) * HDIM + 16 * ks + 2 * lm];
        qf[ks][0] = *(const unsigned*)q1;
        qf[ks][1] = *(const unsigned*)q2;
        qf[ks][2] = *(const unsigned*)(q1 + 8);
        qf[ks][3] = *(const unsigned*)(q2 + 8);
    }

    float oacc[8][4];
#pragma unroll
    for (int i = 0; i < 8; i++)
#pragma unroll
        for (int j = 0; j < 4; j++) oacc[i][j] = 0.f;
    float lsum1 = 0.f, lsum2 = 0.f;

    const int srow0 = tid >> 3, srow1 = (tid + 256) >> 3;
    const int sch = (tid & 7) * 8;

    {
        const __half* Kg = &K[(size_t)c0 * 64 * HDIM];
        const __half* Vg = &V[(size_t)c0 * 64 * HDIM];
        cpa16(sb + (uint32_t)(srow0 * KP + sch) * 2, &Kg[srow0 * HDIM + sch]);
        cpa16(sb + (uint32_t)(srow1 * KP + sch) * 2, &Kg[srow1 * HDIM + sch]);
        cpa16(sb + 2 * KBYTES + (uint32_t)(srow0 * KP + sch) * 2, &Vg[srow0 * HDIM + sch]);
        cpa16(sb + 2 * KBYTES + (uint32_t)(srow1 * KP + sch) * 2, &Vg[srow1 * HDIM + sch]);
        asm volatile("cp.async.commit_group;" ::: "memory");
    }

#pragma unroll 1
    for (int n = c0; n < c1; n++) {
        const int buf = (n - c0) & 1;
        const uint32_t kb_s = sb + buf * KBYTES;
        const uint32_t vb_s = sb + (2 + buf) * KBYTES;

        asm volatile("cp.async.wait_group 0;" ::: "memory");
        __syncthreads();

        if (n + 1 < c1) {
            const int nbuf = 1 - buf;
            const __half* Kg = &K[(size_t)(n + 1) * 64 * HDIM];
            const __half* Vg = &V[(size_t)(n + 1) * 64 * HDIM];
            const uint32_t kd = sb + nbuf * KBYTES;
            const uint32_t vd = sb + (2 + nbuf) * KBYTES;
            cpa16(kd + (uint32_t)(srow0 * KP + sch) * 2, &Kg[srow0 * HDIM + sch]);
            cpa16(kd + (uint32_t)(srow1 * KP + sch) * 2, &Kg[srow1 * HDIM + sch]);
            cpa16(vd + (uint32_t)(srow0 * KP + sch) * 2, &Vg[srow0 * HDIM + sch]);
            cpa16(vd + (uint32_t)(srow1 * KP + sch) * 2, &Vg[srow1 * HDIM + sch]);
            asm volatile("cp.async.commit_group;" ::: "memory");
        }

        float s[4][4];
#pragma unroll
        for (int i = 0; i < 4; i++)
#pragma unroll
            for (int j = 0; j < 4; j++) s[i][j] = 0.f;
#pragma unroll
        for (int np = 0; np < 2; np++) {
            const int n0 = 32 * nw + 16 * np;
#pragma unroll
            for (int ks = 0; ks < 4; ks++) {
                const int h0 = 16 * ks;
                uint32_t ka = kb_s + (uint32_t)((n0 + ((j8 >> 1) << 3) + r8) * KP
                                                + h0 + ((j8 & 1) << 3)) * 2;
                unsigned k0r, k1r, k2r, k3r;
                LDSM_X4(k0r, k1r, k2r, k3r, ka);
                mma16(s[2 * np],     qf[ks], k0r, k1r);
                mma16(s[2 * np + 1], qf[ks], k2r, k3r);
            }
        }

        if (n == m) {
#pragma unroll
            for (int nf = 0; nf < 4; nf++) {
                int lc = 32 * nw + 8 * nf + 2 * lm;
                int lr1 = rb + l4, lr2 = lr1 + 8;
                s[nf][0] = (lc     <= lr1) ? exp2f(s[nf][0] * CFAC) : 0.f;
                s[nf][1] = (lc + 1 <= lr1) ? exp2f(s[nf][1] * CFAC) : 0.f;
                s[nf][2] = (lc     <= lr2) ? exp2f(s[nf][2] * CFAC) : 0.f;
                s[nf][3] = (lc + 1 <= lr2) ? exp2f(s[nf][3] * CFAC) : 0.f;
            }
        } else {
#pragma unroll
            for (int nf = 0; nf < 4; nf++) {
                s[nf][0] = exp2f(s[nf][0] * CFAC);
                s[nf][1] = exp2f(s[nf][1] * CFAC);
                s[nf][2] = exp2f(s[nf][2] * CFAC);
                s[nf][3] = exp2f(s[nf][3] * CFAC);
            }
        }
#pragma unroll
        for (int nf = 0; nf < 4; nf++) {
            lsum1 += s[nf][0] + s[nf][1];
            lsum2 += s[nf][2] + s[nf][3];
        }

        unsigned ap[2][4];
#pragma unroll
        for (int kb = 0; kb < 2; kb++) {
            ap[kb][0] = packh2(s[2 * kb][0],     s[2 * kb][1]);
            ap[kb][1] = packh2(s[2 * kb][2],     s[2 * kb][3]);
            ap[kb][2] = packh2(s[2 * kb + 1][0], s[2 * kb + 1][1]);
            ap[kb][3] = packh2(s[2 * kb + 1][2], s[2 * kb + 1][3]);
        }

#pragma unroll
        for (int kb = 0; kb < 2; kb++) {
            const int k0 = 32 * nw + 16 * kb;
#pragma unroll
            for (int hp = 0; hp < 4; hp++) {
                const int h0 = 16 * hp;
                uint32_t va = vb_s + (uint32_t)((k0 + ((j8 & 1) << 3) + r8) * KP
                                                + h0 + ((j8 >> 1) << 3)) * 2;
                unsigned v0r, v1r, v2r, v3r;
                LDSM_X4_T(v0r, v1r, v2r, v3r, va);
                mma16(oacc[2 * hp],     ap[kb], v0r, v1r);
                mma16(oacc[2 * hp + 1], ap[kb], v2r, v3r);
            }
        }
    }

    // ---- reduce row sums within warp quads ----
    lsum1 += __shfl_xor_sync(0xffffffffu, lsum1, 1);
    lsum1 += __shfl_xor_sync(0xffffffffu, lsum1, 2);
    lsum2 += __shfl_xor_sync(0xffffffffu, lsum2, 1);
    lsum2 += __shfl_xor_sync(0xffffffffu, lsum2, 2);

    if (m < 32) {
        // ---- complete tile: pair-reduce via smem, write normalized out ----
        float* ex  = (float*)smh;             // [64][EXP]
        float* exl = ex + 64 * EXP;           // [64]
        __syncthreads();                      // K/V smem no longer needed
        if (nw == 0) {
#pragma unroll
            for (int hb = 0; hb < 8; hb++) {
                int col = 8 * hb + 2 * lm;
                *(float2*)&ex[(rb + l4) * EXP + col] = make_float2(oacc[hb][0], oacc[hb][1]);
                *(float2*)&ex[(rb + 8 + l4) * EXP + col] = make_float2(oacc[hb][2], oacc[hb][3]);
            }
            if (lm == 0) { exl[rb + l4] = lsum1; exl[rb + 8 + l4] = lsum2; }
        }
        __syncthreads();
        if (nw == 1) {
            float inv1 = 1.0f / (lsum1 + exl[rb + l4]);
            float inv2 = 1.0f / (lsum2 + exl[rb + 8 + l4]);
            float* Og = out + ((size_t)b * TSEQ + q0) * HDIM;
#pragma unroll
            for (int hb = 0; hb < 8; hb++) {
                int col = 8 * hb + 2 * lm;
                float2 e1 = *(const float2*)&ex[(rb + l4) * EXP + col];
                float2 e2 = *(const float2*)&ex[(rb + 8 + l4) * EXP + col];
                *(float2*)&Og[(size_t)(rb + l4) * HDIM + col] =
                    make_float2((oacc[hb][0] + e1.x) * inv1, (oacc[hb][1] + e1.y) * inv1);
                *(float2*)&Og[(size_t)(rb + 8 + l4) * HDIM + col] =
                    make_float2((oacc[hb][2] + e2.x) * inv2, (oacc[hb][3] + e2.y) * inv2);
            }
        }
    } else {
        // ---- split tile: atomic-accumulate partials ----
        if (lm == 0) {
            atomicAdd(&g_lsum[(size_t)b * TSEQ + q0 + rb + l4], lsum1);
            atomicAdd(&g_lsum[(size_t)b * TSEQ + q0 + rb + 8 + l4], lsum2);
        }
        float* Ob = g_osum + (size_t)b * TSEQ * HDIM;
        const size_t r1 = (size_t)(q0 + rb + l4) * HDIM;
        const size_t r2 = (size_t)(q0 + rb + 8 + l4) * HDIM;
#pragma unroll
        for (int hb = 0; hb < 8; hb++) {
            int col = 8 * hb + 2 * lm;
            atomicAdd(&Ob[r1 + col],     oacc[hb][0]);
            atomicAdd(&Ob[r1 + col + 1], oacc[hb][1]);
            atomicAdd(&Ob[r2 + col],     oacc[hb][2]);
            atomicAdd(&Ob[r2 + col + 1], oacc[hb][3]);
        }
    }
}

// ---------------------------------------------------------------------------
// Normalize only rows of split tiles (m>=32): rows [2048,4096) per batch.
// ---------------------------------------------------------------------------
__global__ void norm_kernel(float* __restrict__ out)
{
    int idx = blockIdx.x * blockDim.x + threadIdx.x;   // 0..131071 float4
    int b = idx >> 15, rem = idx & 32767;
    int row = 2048 + (rem >> 4);
    size_t f4 = (((size_t)b * TSEQ + row) * HDIM >> 2) + (rem & 15);
    float4 o = ((const float4*)g_osum)[f4];
    float inv = 1.0f / g_lsum[(size_t)b * TSEQ + row];
    ((float4*)out)[f4] = make_float4(o.x * inv, o.y * inv, o.z * inv, o.w * inv);
}

// ---------------------------------------------------------------------------
extern "C" void kernel_launch(void* const* d_in, const int* in_sizes, int n_in,
                              void* d_out, int out_size)
{
    const float* x  = (const float*)d_in[0];
    const float* Wq = (const float*)d_in[1];
    const float* Wk = (const float*)d_in[2];
    const float* Wv = (const float*)d_in[3];
    float* out = (float*)d_out;

    const int proj_smem = 2 * (64 * XSH + 64 * WSH) * 2;   // 69632 B
    const int attn_smem = 4 * 64 * KP * 2;                 // 36864 B (>= 64*EXP*4+256)
    cudaFuncSetAttribute(proj_kernel, cudaFuncAttributeMaxDynamicSharedMemorySize, proj_smem);
    cudaFuncSetAttribute(attn_kernel, cudaFuncAttributeMaxDynamicSharedMemorySize, attn_smem);

    wcvt_kernel<<<256, 256>>>(Wq, Wk, Wv);
    proj_kernel<<<NB * TSEQ / 64, 256, proj_smem>>>(x);
    attn_kernel<<<384, 256, attn_smem>>>(out);
    norm_kernel<<<512, 256>>>(out);
}